// round 1
// baseline (speedup 1.0000x reference)
#include <cuda_runtime.h>
#include <cuda_bf16.h>

// LightConv: out[b,t,h*S+s] = sum_k softmax_k(filters[b,t,h*K+k]) * x[b, t+k-PAD, h*S+s] + bias[h*S+s]
// B=8 T=1024 H=8 S=64 K=31 C=512

#define B_ 8
#define T_ 1024
#define H_ 8
#define S_ 64
#define K_ 31
#define C_ 512
#define HK_ (H_ * K_)      // 248
#define PAD_ 15            // K/2
#define TTILE 128          // t rows per CTA
#define RT 8               // t outputs per thread
#define NGROUPS (TTILE / RT)   // 16
#define NTHREADS 256           // NGROUPS * 16 (16 float4 lanes cover S=64)
#define XROWS (TTILE + 2 * PAD_)   // 158
#define WSTRIDE 33             // padded: keeps the 2 t-groups of a warp in different banks

#define SMEM_BYTES ((XROWS * S_ + TTILE * WSTRIDE) * 4)   // 40448 + 16896 = 57344

__global__ __launch_bounds__(NTHREADS) void lightconv_kernel(
    const float* __restrict__ x,
    const float* __restrict__ filters,
    const float* __restrict__ bias,
    float* __restrict__ out)
{
    extern __shared__ float smem[];
    float* xs = smem;                    // [XROWS][64]
    float* ws = smem + XROWS * S_;       // [TTILE][WSTRIDE]

    const int t0   = blockIdx.x * TTILE;
    const int h    = blockIdx.y;
    const int b    = blockIdx.z;
    const int tid  = threadIdx.x;
    const int lane = tid & 31;
    const int warp = tid >> 5;

    // ---- load x tile (coalesced), zero-fill halo outside [0, T) ----
    const float* xbase = x + (size_t)b * T_ * C_ + h * S_;
    #pragma unroll 4
    for (int idx = tid; idx < XROWS * S_; idx += NTHREADS) {
        int row = idx >> 6;          // /64
        int col = idx & 63;
        int t   = t0 + row - PAD_;
        float v = 0.0f;
        if (t >= 0 && t < T_) v = xbase[(size_t)t * C_ + col];
        xs[idx] = v;
    }

    // ---- softmax over K=31 taps: one warp per t-row, lane = k ----
    const float* fbase = filters + (size_t)b * T_ * HK_ + h * K_;
    for (int row = warp; row < TTILE; row += NTHREADS / 32) {
        float f = -1e30f;
        if (lane < K_) f = fbase[(size_t)(t0 + row) * HK_ + lane];
        float m = f;
        #pragma unroll
        for (int o = 16; o > 0; o >>= 1)
            m = fmaxf(m, __shfl_xor_sync(0xffffffffu, m, o));
        float e = (lane < K_) ? __expf(f - m) : 0.0f;
        float s = e;
        #pragma unroll
        for (int o = 16; o > 0; o >>= 1)
            s += __shfl_xor_sync(0xffffffffu, s, o);
        if (lane < K_) ws[row * WSTRIDE + lane] = e * (1.0f / s);
    }
    __syncthreads();

    // ---- main product: thread = (s4 lane: 4 channels) x (tg: 8 t outputs) ----
    const int s4 = tid & 15;       // float4 lane within 64 channels
    const int tg = tid >> 4;       // 0..15
    const int tl = tg * RT;        // local t base

    const float4* xs4 = reinterpret_cast<const float4*>(xs);

    float4 acc[RT];
    #pragma unroll
    for (int r = 0; r < RT; ++r) acc[r] = make_float4(0.f, 0.f, 0.f, 0.f);

    // j-form: each xs float4 loaded once, feeds up to RT accumulators.
    #pragma unroll
    for (int j = 0; j < RT + K_ - 1; ++j) {
        float4 xj = xs4[(tl + j) * (S_ / 4) + s4];
        #pragma unroll
        for (int r = 0; r < RT; ++r) {
            const int k = j - r;
            if (k >= 0 && k < K_) {
                float w = ws[(tl + r) * WSTRIDE + k];
                acc[r].x = fmaf(w, xj.x, acc[r].x);
                acc[r].y = fmaf(w, xj.y, acc[r].y);
                acc[r].z = fmaf(w, xj.z, acc[r].z);
                acc[r].w = fmaf(w, xj.w, acc[r].w);
            }
        }
    }

    // ---- epilogue: + bias, vectorized store ----
    float4 bv = reinterpret_cast<const float4*>(bias + h * S_)[s4];
    float4* outbase = reinterpret_cast<float4*>(
        out + ((size_t)b * T_ + t0 + tl) * C_ + h * S_);
    #pragma unroll
    for (int r = 0; r < RT; ++r) {
        float4 o;
        o.x = acc[r].x + bv.x;
        o.y = acc[r].y + bv.y;
        o.z = acc[r].z + bv.z;
        o.w = acc[r].w + bv.w;
        outbase[(size_t)r * (C_ / 4) + s4] = o;
    }
}

extern "C" void kernel_launch(void* const* d_in, const int* in_sizes, int n_in,
                              void* d_out, int out_size)
{
    const float* x       = (const float*)d_in[0];
    const float* filters = (const float*)d_in[1];
    const float* bias    = (const float*)d_in[2];
    float* out           = (float*)d_out;

    cudaFuncSetAttribute(lightconv_kernel,
                         cudaFuncAttributeMaxDynamicSharedMemorySize, SMEM_BYTES);

    dim3 grid(T_ / TTILE, H_, B_);   // (8, 8, 8)
    lightconv_kernel<<<grid, NTHREADS, SMEM_BYTES>>>(x, filters, bias, out);
}

// round 2
// speedup vs baseline: 2.1478x; 2.1478x over previous
#include <cuda_runtime.h>
#include <cuda_bf16.h>

// LightConv: out[b,t,h*S+s] = sum_k softmax_k(filters[b,t,h*K+k]) * x[b, t+k-PAD, h*S+s] + bias[h*S+s]
// B=8 T=1024 H=8 S=64 K=31 C=512

#define B_ 8
#define T_ 1024
#define H_ 8
#define S_ 64
#define K_ 31
#define C_ 512
#define HK_ (H_ * K_)      // 248
#define PAD_ 15            // K/2
#define TTILE 128          // t rows per CTA
#define RT 8               // t outputs per thread
#define NTHREADS 256       // 16 t-groups x 16 float4 lanes
#define XROWS (TTILE + 2 * PAD_)   // 158
#define WSTRIDE 129        // k-major weights: ws[k*129 + row]; stride 129 -> conflict-free

// xs: 158*64*4 = 40448 B ; ws: (30*129+127+1)*4 = 16000 B ; total 56448 B -> 4 CTAs/SM
#define WS_FLOATS (30 * WSTRIDE + TTILE)
#define SMEM_BYTES ((XROWS * S_ + WS_FLOATS) * 4)

__device__ __forceinline__ unsigned long long pack2(float w) {
    unsigned long long d;
    asm("mov.b64 %0, {%1, %1};" : "=l"(d) : "f"(w));
    return d;
}
__device__ __forceinline__ void fma2(unsigned long long& a, unsigned long long x,
                                     unsigned long long w) {
    asm("fma.rn.f32x2 %0, %1, %2, %3;" : "=l"(a) : "l"(x), "l"(w), "l"(a));
}
__device__ __forceinline__ float2 unpack2(unsigned long long v) {
    float2 f;
    asm("mov.b64 {%0, %1}, %2;" : "=f"(f.x), "=f"(f.y) : "l"(v));
    return f;
}

__global__ __launch_bounds__(NTHREADS, 4) void lightconv_kernel(
    const float* __restrict__ x,
    const float* __restrict__ filters,
    const float* __restrict__ bias,
    float* __restrict__ out)
{
    extern __shared__ float smem[];
    float* xs = smem;                    // [XROWS][64]
    float* ws = smem + XROWS * S_;       // k-major: [K][TTILE] stride 129

    const int t0   = blockIdx.x * TTILE;
    const int h    = blockIdx.y;
    const int b    = blockIdx.z;
    const int tid  = threadIdx.x;
    const int lane = tid & 31;
    const int warp = tid >> 5;

    // ---- load x tile (coalesced), zero-fill halo outside [0, T) ----
    const float* xbase = x + (size_t)b * T_ * C_ + h * S_;
    #pragma unroll 4
    for (int idx = tid; idx < XROWS * S_; idx += NTHREADS) {
        int row = idx >> 6;
        int col = idx & 63;
        int t   = t0 + row - PAD_;
        float v = 0.0f;
        if (t >= 0 && t < T_) v = xbase[(size_t)t * C_ + col];
        xs[idx] = v;
    }

    // ---- softmax over K=31 taps: warp per t-row, lane = k; 2 rows/iter for ILP ----
    const float* fbase = filters + (size_t)b * T_ * HK_ + h * K_;
    for (int row = warp; row < TTILE; row += 16) {
        int rowB = row + 8;
        float fA = -1e30f, fB = -1e30f;
        if (lane < K_) {
            fA = fbase[(size_t)(t0 + row)  * HK_ + lane];
            fB = fbase[(size_t)(t0 + rowB) * HK_ + lane];
        }
        float mA = fA, mB = fB;
        #pragma unroll
        for (int o = 16; o > 0; o >>= 1) {
            mA = fmaxf(mA, __shfl_xor_sync(0xffffffffu, mA, o));
            mB = fmaxf(mB, __shfl_xor_sync(0xffffffffu, mB, o));
        }
        float eA = (lane < K_) ? __expf(fA - mA) : 0.0f;
        float eB = (lane < K_) ? __expf(fB - mB) : 0.0f;
        float sA = eA, sB = eB;
        #pragma unroll
        for (int o = 16; o > 0; o >>= 1) {
            sA += __shfl_xor_sync(0xffffffffu, sA, o);
            sB += __shfl_xor_sync(0xffffffffu, sB, o);
        }
        if (lane < K_) {
            ws[lane * WSTRIDE + row]  = eA * (1.0f / sA);   // banks = lane -> conflict-free
            ws[lane * WSTRIDE + rowB] = eB * (1.0f / sB);
        }
    }
    __syncthreads();

    // ---- main product ----
    // thread = (s4: 4 channels as 2x f32x2) x (tg: RT t outputs)
    const int s4 = tid & 15;
    const int tg = tid >> 4;
    const int tl = tg * RT;

    const ulonglong2* xs2 = reinterpret_cast<const ulonglong2*>(xs) + s4;
    const float* wcol = ws + tl;   // w[t=tl+r][k=j-r] at wcol[j*WSTRIDE - (WSTRIDE-1)*r]

    unsigned long long acc[RT][2];
    #pragma unroll
    for (int r = 0; r < RT; ++r) { acc[r][0] = 0ull; acc[r][1] = 0ull; }

    // Region 1: j = 0 .. RT-2 (triangular, fully unrolled, compile-time guards)
    #pragma unroll
    for (int j = 0; j < RT - 1; ++j) {
        ulonglong2 xv = xs2[(tl + j) * (S_ / 4)];
        #pragma unroll
        for (int r = 0; r < RT; ++r) {
            if (r <= j) {
                unsigned long long w2 = pack2(wcol[j * WSTRIDE - (WSTRIDE - 1) * r]);
                fma2(acc[r][0], xv.x, w2);
                fma2(acc[r][1], xv.y, w2);
            }
        }
    }

    // Region 2: j = RT-1 .. K-1 (steady state: all r valid, NO predicates)
    #pragma unroll 4
    for (int j = RT - 1; j < K_; ++j) {
        ulonglong2 xv = xs2[(tl + j) * (S_ / 4)];
        #pragma unroll
        for (int r = 0; r < RT; ++r) {
            unsigned long long w2 = pack2(wcol[j * WSTRIDE - (WSTRIDE - 1) * r]);
            fma2(acc[r][0], xv.x, w2);
            fma2(acc[r][1], xv.y, w2);
        }
    }

    // Region 3: j = K .. K+RT-2 (triangular, fully unrolled, compile-time guards)
    #pragma unroll
    for (int j = K_; j < K_ + RT - 1; ++j) {
        ulonglong2 xv = xs2[(tl + j) * (S_ / 4)];
        #pragma unroll
        for (int r = 0; r < RT; ++r) {
            if (j - r < K_) {
                unsigned long long w2 = pack2(wcol[j * WSTRIDE - (WSTRIDE - 1) * r]);
                fma2(acc[r][0], xv.x, w2);
                fma2(acc[r][1], xv.y, w2);
            }
        }
    }

    // ---- epilogue: + bias, vectorized store ----
    float4 bv = reinterpret_cast<const float4*>(bias + h * S_)[s4];
    float4* outbase = reinterpret_cast<float4*>(
        out + ((size_t)b * T_ + t0 + tl) * C_ + h * S_) + s4;
    #pragma unroll
    for (int r = 0; r < RT; ++r) {
        float2 lo = unpack2(acc[r][0]);
        float2 hi = unpack2(acc[r][1]);
        float4 o;
        o.x = lo.x + bv.x;
        o.y = lo.y + bv.y;
        o.z = hi.x + bv.z;
        o.w = hi.y + bv.w;
        outbase[(size_t)r * (C_ / 4)] = o;
    }
}

extern "C" void kernel_launch(void* const* d_in, const int* in_sizes, int n_in,
                              void* d_out, int out_size)
{
    const float* x       = (const float*)d_in[0];
    const float* filters = (const float*)d_in[1];
    const float* bias    = (const float*)d_in[2];
    float* out           = (float*)d_out;

    cudaFuncSetAttribute(lightconv_kernel,
                         cudaFuncAttributeMaxDynamicSharedMemorySize, SMEM_BYTES);

    dim3 grid(T_ / TTILE, H_, B_);   // (8, 8, 8) = 512 CTAs -> single wave at 4 CTAs/SM
    lightconv_kernel<<<grid, NTHREADS, SMEM_BYTES>>>(x, filters, bias, out);
}